// round 2
// baseline (speedup 1.0000x reference)
#include <cuda_runtime.h>
#include <cuda_bf16.h>

// Problem constants
#define BDIM 2048   // batch rows
#define SDIM 1024   // support vectors
#define FDIM 64     // features

// Tiling for main kernel
#define BM 64       // rows per block tile
#define BN 16       // support cols per chunk
#define TM 2        // rows per thread
#define TN 4        // cols per thread
#define NTHREADS 128
#define SSPLIT 16   // grid.y splits over support dim (each block covers 1024/16 = 64 support)

// Precomputed half-angle trig tables, TRANSPOSED: [f][i] so kernel B shared
// fills are coalesced and LDS reads are conflict-free / vectorizable.
// x = cos(v/2), y = sin(v/2)
__device__ float2 g_X2t[FDIM * BDIM];   // 1 MB
__device__ float2 g_S2t[FDIM * SDIM];   // 512 KB

// ---------------------------------------------------------------------------
// Kernel A: precompute trig tables + initialize out[i] = b[0]
// ---------------------------------------------------------------------------
__global__ void precompute_kernel(const float* __restrict__ X,
                                  const float* __restrict__ S,
                                  const float* __restrict__ b,
                                  float* __restrict__ out) {
    int idx = blockIdx.x * blockDim.x + threadIdx.x;

    const int NX = FDIM * BDIM;     // 131072
    const int NS = FDIM * SDIM;     // 65536

    if (idx < NX) {
        int f = idx >> 11;          // idx / 2048
        int i = idx & (BDIM - 1);   // idx % 2048
        float v = X[i * FDIM + f];
        float s, c;
        __sincosf(0.5f * v, &s, &c);
        g_X2t[idx] = make_float2(c, s);
    } else if (idx < NX + NS) {
        int e = idx - NX;
        int f = e >> 10;            // e / 1024
        int j = e & (SDIM - 1);     // e % 1024
        float v = S[j * FDIM + f];
        float s, c;
        __sincosf(0.5f * v, &s, &c);
        g_S2t[e] = make_float2(c, s);
    }

    if (idx < BDIM) {
        out[idx] = b[0];            // atomics in kernel B accumulate on top
    }
}

// ---------------------------------------------------------------------------
// Kernel B: tiled product-kernel + weighted reduction
//   grid = (BDIM/BM = 32, SSPLIT = 16), block = 128 threads
//   thread (tx = tid&3, ty = tid>>2) owns TM=2 rows x TN=4 cols.
// ---------------------------------------------------------------------------
__global__ __launch_bounds__(NTHREADS)
void qkr_main_kernel(const float* __restrict__ W,
                     float* __restrict__ out) {
    __shared__ float2 sX[FDIM][BM];   // 32 KB
    __shared__ float2 sS[FDIM][BN];   //  8 KB

    const int tid = threadIdx.x;
    const int tx = tid & 3;           // 0..3  -> j group
    const int ty = tid >> 2;          // 0..31 -> i group
    const int rowbase = blockIdx.x * BM;
    const int row0 = ty * TM;         // even -> 16B-aligned float4 loads
    const int col0 = tx * TN;         // multiple of 4 -> 16B-aligned

    // Fill sX: 64x64 float2 = 4096 elems, 32 per thread, coalesced
    #pragma unroll
    for (int e = tid; e < FDIM * BM; e += NTHREADS) {
        int f = e >> 6;
        int r = e & (BM - 1);
        sX[f][r] = g_X2t[f * BDIM + rowbase + r];
    }

    float acc[TM];
    #pragma unroll
    for (int m = 0; m < TM; m++) acc[m] = 0.0f;

    const int jsplit_base = blockIdx.y * (SDIM / SSPLIT);   // 64 support per block

    for (int chunk = 0; chunk < (SDIM / SSPLIT) / BN; chunk++) {   // 4 chunks
        const int jbase = jsplit_base + chunk * BN;

        __syncthreads();   // protect sS overwrite (and covers sX on chunk 0)
        #pragma unroll
        for (int e = tid; e < FDIM * BN; e += NTHREADS) {          // 8 per thread
            int f = e >> 4;
            int c = e & (BN - 1);
            sS[f][c] = g_S2t[f * SDIM + jbase + c];
        }
        __syncthreads();

        float p[TM][TN];
        #pragma unroll
        for (int m = 0; m < TM; m++)
            #pragma unroll
            for (int n = 0; n < TN; n++) p[m][n] = 1.0f;

        #pragma unroll 8
        for (int f = 0; f < FDIM; f++) {
            // rows: 2 float2 = one float4
            float4 xa = *(const float4*)&sX[f][row0];
            // cols: 4 float2 = two float4
            float4 sa = *(const float4*)&sS[f][col0];
            float4 sb = *(const float4*)&sS[f][col0 + 2];

            float xc[TM] = { xa.x, xa.z };
            float xs[TM] = { xa.y, xa.w };
            float sc[TN] = { sa.x, sa.z, sb.x, sb.z };
            float ss[TN] = { sa.y, sa.w, sb.y, sb.w };

            #pragma unroll
            for (int m = 0; m < TM; m++) {
                #pragma unroll
                for (int n = 0; n < TN; n++) {
                    float c = fmaf(xs[m], ss[n], xc[m] * sc[n]);  // cos(a-b)
                    p[m][n] *= c;                                 // signed product
                }
            }
        }

        // apply weights; K = (prod cos)^2 = prod cos^2
        float wv[TN];
        #pragma unroll
        for (int n = 0; n < TN; n++) wv[n] = __ldg(&W[jbase + col0 + n]);

        #pragma unroll
        for (int m = 0; m < TM; m++)
            #pragma unroll
            for (int n = 0; n < TN; n++)
                acc[m] = fmaf(wv[n], p[m][n] * p[m][n], acc[m]);
    }

    // Reduce across the 4 tx lanes (consecutive lanes share the same rows)
    #pragma unroll
    for (int off = 1; off < 4; off <<= 1) {
        #pragma unroll
        for (int m = 0; m < TM; m++)
            acc[m] += __shfl_xor_sync(0xffffffffu, acc[m], off);
    }

    if (tx == 0) {
        #pragma unroll
        for (int m = 0; m < TM; m++)
            atomicAdd(&out[rowbase + row0 + m], acc[m]);
    }
}

// ---------------------------------------------------------------------------
extern "C" void kernel_launch(void* const* d_in, const int* in_sizes, int n_in,
                              void* d_out, int out_size) {
    const float* X = (const float*)d_in[0];   // [2048, 64]
    const float* S = (const float*)d_in[1];   // [1024, 64]
    const float* W = (const float*)d_in[2];   // [1, 1024]
    const float* b = (const float*)d_in[3];   // [1]
    float* out = (float*)d_out;               // [2048]

    // Kernel A: trig tables + out init
    {
        int total = FDIM * BDIM + FDIM * SDIM;   // 196608
        int threads = 256;
        int blocks = (total + threads - 1) / threads;
        precompute_kernel<<<blocks, threads>>>(X, S, b, out);
    }

    // Kernel B: main tiled compute
    {
        dim3 grid(BDIM / BM, SSPLIT);   // (32, 16)
        qkr_main_kernel<<<grid, NTHREADS>>>(W, out);
    }
}

// round 3
// speedup vs baseline: 1.2074x; 1.2074x over previous
#include <cuda_runtime.h>
#include <cuda_bf16.h>

// Problem constants
#define BDIM 2048   // batch rows
#define SDIM 1024   // support vectors
#define FDIM 64     // features

// Tiling
#define BM 64       // rows per block (warp lanes = 32 rows x 2 row-groups)
#define BN 32       // support cols per smem chunk
#define TN 8        // cols per warp (4 warps x 8 = 32 = BN)
#define NTHREADS 128
#define SSPLIT 16   // grid.y; each block covers 1024/16 = 64 S = 2 chunks

// Precomputed half-angle trig tables, SoA + transposed [f][elem]:
// coalesced smem fills, conflict-free lane-unique X loads, packed-pair S loads.
__device__ float g_Xc[FDIM * BDIM];
__device__ float g_Xs[FDIM * BDIM];
__device__ float g_Sc[FDIM * SDIM];
__device__ float g_Ss[FDIM * SDIM];

// ---- packed f32x2 helpers (ptxas will NOT auto-fuse; PTX only) --------------
#define MUL2(d, a, b) \
    asm("mul.rn.f32x2 %0, %1, %2;" : "=l"(d) : "l"(a), "l"(b))
#define FMA2(d, a, b, c) \
    asm("fma.rn.f32x2 %0, %1, %2, %3;" : "=l"(d) : "l"(a), "l"(b), "l"(c))
#define SPLAT2(d, x) \
    asm("mov.b64 %0, {%1, %1};" : "=l"(d) : "r"(__float_as_uint(x)))
#define UNPACK2(lo, hi, d) \
    asm("mov.b64 {%0, %1}, %2;" : "=r"(lo), "=r"(hi) : "l"(d))

// ---------------------------------------------------------------------------
// Kernel A: precompute trig tables + initialize out[i] = b[0]
// ---------------------------------------------------------------------------
__global__ void precompute_kernel(const float* __restrict__ X,
                                  const float* __restrict__ S,
                                  const float* __restrict__ b,
                                  float* __restrict__ out) {
    int idx = blockIdx.x * blockDim.x + threadIdx.x;

    const int NX = FDIM * BDIM;     // 131072
    const int NS = FDIM * SDIM;     // 65536

    if (idx < NX) {
        int f = idx >> 11;          // / 2048
        int i = idx & (BDIM - 1);
        float v = X[i * FDIM + f];
        float s, c;
        __sincosf(0.5f * v, &s, &c);
        g_Xc[idx] = c;
        g_Xs[idx] = s;
    } else if (idx < NX + NS) {
        int e = idx - NX;
        int f = e >> 10;            // / 1024
        int j = e & (SDIM - 1);
        float v = S[j * FDIM + f];
        float s, c;
        __sincosf(0.5f * v, &s, &c);
        g_Sc[e] = c;
        g_Ss[e] = s;
    }

    if (idx < BDIM) {
        out[idx] = b[0];            // global atomics accumulate on top
    }
}

// ---------------------------------------------------------------------------
// Kernel B: grid (2048/64, 16), 128 threads (4 warps).
//   Warp lanes = 32 distinct rows (x2 row-groups: lane, lane+32)
//     -> X LDS.32 loads are lane-unique (no broadcast waste).
//   Warp w owns cols [w*8, w*8+8) of the BN=32 chunk
//     -> S LDS.128 loads are all-lanes-same-address (1 wavefront each).
//   Inner math in packed f32x2 (2 MACs/lane/instr).
// ---------------------------------------------------------------------------
__global__ __launch_bounds__(NTHREADS)
void qkr_main_kernel(const float* __restrict__ W,
                     float* __restrict__ out) {
    __shared__ __align__(16) float sXc[FDIM][BM];   // 16 KB
    __shared__ __align__(16) float sXs[FDIM][BM];   // 16 KB
    __shared__ __align__(16) float sSc[FDIM][BN];   //  8 KB
    __shared__ __align__(16) float sSs[FDIM][BN];   //  8 KB
    __shared__ float rowacc[BM];

    const int tid  = threadIdx.x;
    const int lane = tid & 31;
    const int warp = tid >> 5;          // 0..3
    const int col0 = warp * TN;         // 0,8,16,24 (16B aligned in sS rows)
    const int rowbase = blockIdx.x * BM;

    // Fill X tiles: 2 x 4096 floats, 32 per thread, coalesced
    #pragma unroll
    for (int e = tid; e < FDIM * BM; e += NTHREADS) {
        int f = e >> 6;
        int r = e & (BM - 1);
        sXc[f][r] = g_Xc[f * BDIM + rowbase + r];
        sXs[f][r] = g_Xs[f * BDIM + rowbase + r];
    }
    if (tid < BM) rowacc[tid] = 0.0f;

    float acc0 = 0.0f, acc1 = 0.0f;     // row-group accumulators

    const int jsplit_base = blockIdx.y * (SDIM / SSPLIT);   // 64 S per block

    for (int chunk = 0; chunk < (SDIM / SSPLIT) / BN; chunk++) {   // 2 chunks
        const int jbase = jsplit_base + chunk * BN;

        __syncthreads();   // protect sS overwrite (covers sX fill on chunk 0)
        #pragma unroll
        for (int e = tid; e < FDIM * BN; e += NTHREADS) {          // 16/thread
            int f = e >> 5;
            int c = e & (BN - 1);
            sSc[f][c] = g_Sc[f * SDIM + jbase + c];
            sSs[f][c] = g_Ss[f * SDIM + jbase + c];
        }
        __syncthreads();

        // packed products: p[m][np] = prod_f cos((x - s)/2) for col pair np
        unsigned long long p[2][4];
        #pragma unroll
        for (int m = 0; m < 2; m++)
            #pragma unroll
            for (int np = 0; np < 4; np++)
                SPLAT2(p[m][np], 1.0f);

        #pragma unroll 8
        for (int f = 0; f < FDIM; f++) {
            // X: lane-unique scalars -> splats
            unsigned long long xc2[2], xs2[2];
            SPLAT2(xc2[0], sXc[f][lane]);
            SPLAT2(xs2[0], sXs[f][lane]);
            SPLAT2(xc2[1], sXc[f][lane + 32]);
            SPLAT2(xs2[1], sXs[f][lane + 32]);

            // S: broadcast 128-bit loads -> two packed pairs each
            ulonglong2 scA = *(const ulonglong2*)&sSc[f][col0];
            ulonglong2 scB = *(const ulonglong2*)&sSc[f][col0 + 4];
            ulonglong2 ssA = *(const ulonglong2*)&sSs[f][col0];
            ulonglong2 ssB = *(const ulonglong2*)&sSs[f][col0 + 4];
            unsigned long long sc[4] = { scA.x, scA.y, scB.x, scB.y };
            unsigned long long ss[4] = { ssA.x, ssA.y, ssB.x, ssB.y };

            #pragma unroll
            for (int m = 0; m < 2; m++) {
                #pragma unroll
                for (int np = 0; np < 4; np++) {
                    unsigned long long t;
                    MUL2(t, xc2[m], sc[np]);        // xc*sc
                    FMA2(t, xs2[m], ss[np], t);     // + xs*ss = cos((x-s)/2)
                    MUL2(p[m][np], p[m][np], t);    // signed running product
                }
            }
        }

        // epilogue: K = (prod cos)^2 ; acc += W[j] * K
        #pragma unroll
        for (int np = 0; np < 4; np++) {
            int jc = jbase + col0 + np * 2;
            float w0 = __ldg(&W[jc]);
            float w1 = __ldg(&W[jc + 1]);

            unsigned int a, b_;
            UNPACK2(a, b_, p[0][np]);
            float pa = __uint_as_float(a), pb = __uint_as_float(b_);
            acc0 = fmaf(w0, pa * pa, acc0);
            acc0 = fmaf(w1, pb * pb, acc0);

            UNPACK2(a, b_, p[1][np]);
            pa = __uint_as_float(a); pb = __uint_as_float(b_);
            acc1 = fmaf(w0, pa * pa, acc1);
            acc1 = fmaf(w1, pb * pb, acc1);
        }
    }

    // Block-level row reduction in shared (4 warps hit each row), then
    // one global atomic per row per block (32 blocks/row total).
    atomicAdd(&rowacc[lane], acc0);
    atomicAdd(&rowacc[lane + 32], acc1);
    __syncthreads();
    if (tid < BM) {
        atomicAdd(&out[rowbase + tid], rowacc[tid]);
    }
}

// ---------------------------------------------------------------------------
extern "C" void kernel_launch(void* const* d_in, const int* in_sizes, int n_in,
                              void* d_out, int out_size) {
    const float* X = (const float*)d_in[0];   // [2048, 64]
    const float* S = (const float*)d_in[1];   // [1024, 64]
    const float* W = (const float*)d_in[2];   // [1, 1024]
    const float* b = (const float*)d_in[3];   // [1]
    float* out = (float*)d_out;               // [2048]

    {
        int total = FDIM * BDIM + FDIM * SDIM;   // 196608
        int threads = 256;
        int blocks = (total + threads - 1) / threads;
        precompute_kernel<<<blocks, threads>>>(X, S, b, out);
    }
    {
        dim3 grid(BDIM / BM, SSPLIT);   // (32, 16) = 512 blocks
        qkr_main_kernel<<<grid, NTHREADS>>>(W, out);
    }
}